// round 1
// baseline (speedup 1.0000x reference)
#include <cuda_runtime.h>
#include <math.h>

// ---------------- problem constants ----------------
#define BATCH 2
#define SEQN  2048
#define DIM   256
#define HID   1024
#define CH    64
#define NCHK  32            // chunks per batch
#define TOKS  (BATCH*SEQN)  // 4096
#define CBTOT (BATCH*NCHK)  // 64 chunk-batches
#define EPSV  1e-6f

// ---------------- device scratch ----------------
__device__ float d_store[TOKS*DIM];
__device__ float d_ret  [TOKS*DIM];
__device__ float d_kbuf [TOKS*DIM];
__device__ float d_vbuf [TOKS*DIM];
__device__ float d_qbuf [TOKS*DIM];
__device__ float d_lr   [TOKS];
__device__ float d_momg [CBTOT];
__device__ float d_decg [CBTOT];
__device__ float d_hbuf [TOKS*HID];
__device__ float d_abuf [TOKS*HID];
__device__ float d_ybuf [TOKS*DIM];
__device__ float d_dybuf[TOKS*DIM];
__device__ float d_dhbuf[TOKS*HID];
__device__ float d_gw1  [CBTOT*DIM*HID];
__device__ float d_gw2  [CBTOT*DIM*HID];
__device__ float d_grn  [CBTOT*DIM];
__device__ float d_w1u  [CBTOT*DIM*HID];
__device__ float d_w2u  [CBTOT*DIM*HID];
__device__ float d_rnu  [CBTOT*DIM];
__device__ float d_a2   [TOKS*HID];
__device__ float d_y2   [TOKS*DIM];

// ---------------- math helpers ----------------
__device__ __forceinline__ float gelu_f(float x) {
    return 0.5f * x * (1.f + erff(x * 0.70710678118654752f));
}
__device__ __forceinline__ float gelu_grad_f(float x) {
    float cdf = 0.5f * (1.f + erff(x * 0.70710678118654752f));
    float pdf = 0.3989422804014327f * expf(-0.5f * x * x);
    return cdf + x * pdf;
}
__device__ __forceinline__ float sigmoid_f(float x) {
    return 1.f / (1.f + expf(-x));
}

// ---------------- preprocessing: rmsnorm, lr, pooled gates ----------------
__global__ void pre_kernel(const float* __restrict__ seq,
                           const float* __restrict__ gs, const float* __restrict__ gr,
                           const float* __restrict__ Wstep, const float* __restrict__ bstep,
                           const float* __restrict__ Wmom,  const float* __restrict__ bmom,
                           const float* __restrict__ Wdec,  const float* __restrict__ bdec,
                           float* __restrict__ store, float* __restrict__ ret,
                           float* __restrict__ lr, float* __restrict__ momg,
                           float* __restrict__ decg)
{
    int cb = blockIdx.x;
    int tid = threadIdx.x, lane = tid & 31, wid = tid >> 5;
    __shared__ float s_gs[DIM], s_gr[DIM], s_ws[DIM];
    __shared__ float r1[DIM], r2[DIM];
    s_gs[tid] = gs[tid]; s_gr[tid] = gr[tid]; s_ws[tid] = Wstep[tid];
    __syncthreads();
    long long base = (long long)cb * CH;
    for (int i = wid; i < CH; i += 8) {
        long long t = base + i;
        float x[8], ss = 0.f;
        #pragma unroll
        for (int j = 0; j < 8; j++) { x[j] = seq[t*DIM + lane + 32*j]; ss += x[j]*x[j]; }
        #pragma unroll
        for (int o = 16; o; o >>= 1) ss += __shfl_xor_sync(0xffffffffu, ss, o);
        float inv = rsqrtf(ss * (1.f/DIM) + EPSV);
        float la = 0.f;
        #pragma unroll
        for (int j = 0; j < 8; j++) {
            int d = lane + 32*j;
            float sn = x[j] * inv;
            float sv = sn * s_gs[d];
            store[t*DIM + d] = sv;
            ret  [t*DIM + d] = sn * s_gr[d];
            la += sv * s_ws[d];
        }
        #pragma unroll
        for (int o = 16; o; o >>= 1) la += __shfl_xor_sync(0xffffffffu, la, o);
        if (lane == 0) lr[t] = sigmoid_f(la + bstep[0]);
    }
    __syncthreads();
    // pooled mean per dim
    int d = tid;
    float p = 0.f;
    for (int i = 0; i < CH; i++) p += store[(base + i)*DIM + d];
    p *= (1.f/CH);
    r1[d] = p * Wmom[d];
    r2[d] = p * Wdec[d];
    __syncthreads();
    for (int s = 128; s; s >>= 1) {
        if (tid < s) { r1[tid] += r1[tid+s]; r2[tid] += r2[tid+s]; }
        __syncthreads();
    }
    if (tid == 0) {
        momg[cb] = sigmoid_f(r1[0] + bmom[0]);
        decg[cb] = sigmoid_f(r2[0] + bdec[0]);
    }
}

// ---------------- generic tiled fp32 GEMM ----------------
// C[M,N] = op(A)[M,K] * op(B)[K,N]; TA: A[m,k]=A[k*lda+m]; TB: B[k,n]=B[n*ldb+k]
// EPI 0: C=acc | 1: C2=acc, C=gelu(acc) | 2: C=gelu(acc) | 3: C=acc*gelu'(H)
template<bool TA, bool TB, int EPI>
__global__ void gemm_kernel(const float* __restrict__ A, const float* __restrict__ B,
                            float* __restrict__ C, float* __restrict__ C2,
                            const float* __restrict__ H,
                            int M, int N, int K, int lda, int ldb, int ldc,
                            long long sA, long long sB, long long sC)
{
    __shared__ float As[16][68];
    __shared__ float Bs[16][68];
    long long bz = blockIdx.z;
    A += bz * sA; B += bz * sB;
    const int tid = threadIdx.x;
    const int tx = tid & 15, ty = tid >> 4;
    const int m0 = blockIdx.y * 64, n0 = blockIdx.x * 64;
    float acc[4][4] = {};
    for (int k0 = 0; k0 < K; k0 += 16) {
        if (!TA) {
            int m = tid >> 2, kq = (tid & 3) * 4;
            float4 v = *(const float4*)&A[(long long)(m0 + m)*lda + k0 + kq];
            As[kq+0][m] = v.x; As[kq+1][m] = v.y; As[kq+2][m] = v.z; As[kq+3][m] = v.w;
        } else {
            int k = tid >> 4, mq = (tid & 15) * 4;
            float4 v = *(const float4*)&A[(long long)(k0 + k)*lda + m0 + mq];
            As[k][mq+0] = v.x; As[k][mq+1] = v.y; As[k][mq+2] = v.z; As[k][mq+3] = v.w;
        }
        if (!TB) {
            int k = tid >> 4, nq = (tid & 15) * 4;
            float4 v = *(const float4*)&B[(long long)(k0 + k)*ldb + n0 + nq];
            Bs[k][nq+0] = v.x; Bs[k][nq+1] = v.y; Bs[k][nq+2] = v.z; Bs[k][nq+3] = v.w;
        } else {
            int n = tid >> 2, kq = (tid & 3) * 4;
            float4 v = *(const float4*)&B[(long long)(n0 + n)*ldb + k0 + kq];
            Bs[kq+0][n] = v.x; Bs[kq+1][n] = v.y; Bs[kq+2][n] = v.z; Bs[kq+3][n] = v.w;
        }
        __syncthreads();
        #pragma unroll
        for (int k = 0; k < 16; k++) {
            float a[4], b[4];
            #pragma unroll
            for (int i = 0; i < 4; i++) a[i] = As[k][ty*4 + i];
            #pragma unroll
            for (int j = 0; j < 4; j++) b[j] = Bs[k][tx*4 + j];
            #pragma unroll
            for (int i = 0; i < 4; i++)
                #pragma unroll
                for (int j = 0; j < 4; j++)
                    acc[i][j] += a[i] * b[j];
        }
        __syncthreads();
    }
    C += bz * sC;
    if (EPI == 1) C2 += bz * sC;
    if (EPI == 3) H  += bz * sC;
    #pragma unroll
    for (int i = 0; i < 4; i++) {
        #pragma unroll
        for (int j = 0; j < 4; j++) {
            long long idx = (long long)(m0 + ty*4 + i)*ldc + n0 + tx*4 + j;
            float v = acc[i][j];
            if (EPI == 0) C[idx] = v;
            else if (EPI == 1) { C2[idx] = v; C[idx] = gelu_f(v); }
            else if (EPI == 2) C[idx] = gelu_f(v);
            else               C[idx] = v * gelu_grad_f(H[idx]);
        }
    }
}

// ---------------- loss backward through ResidualNorm ----------------
__global__ void lossback_kernel(const float* __restrict__ y, const float* __restrict__ kbuf,
                                const float* __restrict__ vbuf, const float* __restrict__ lr,
                                const float* __restrict__ rn,
                                float* __restrict__ dy, float* __restrict__ grn)
{
    int cb = blockIdx.x;
    int tid = threadIdx.x, lane = tid & 31, wid = tid >> 5;
    __shared__ float s_rn[DIM];
    __shared__ float racc[DIM];
    s_rn[tid] = rn[tid]; racc[tid] = 0.f;
    __syncthreads();
    long long base = (long long)cb * CH;
    float ra[8] = {};
    for (int i = wid; i < CH; i += 8) {
        long long t = base + i;
        float yv[8], ss = 0.f;
        #pragma unroll
        for (int j = 0; j < 8; j++) { yv[j] = y[t*DIM + lane + 32*j]; ss += yv[j]*yv[j]; }
        #pragma unroll
        for (int o = 16; o; o >>= 1) ss += __shfl_xor_sync(0xffffffffu, ss, o);
        float inv = rsqrtf(ss * (1.f/DIM) + EPSV);
        float coef = lr[t] * (2.f/DIM);
        float dyn[8], yn[8], s2 = 0.f;
        #pragma unroll
        for (int j = 0; j < 8; j++) {
            int d = lane + 32*j;
            yn[j] = yv[j] * inv;
            float e = yn[j]*s_rn[d] + kbuf[t*DIM + d] - vbuf[t*DIM + d];
            float dp = coef * e;
            ra[j] += dp * yn[j];
            dyn[j] = dp * s_rn[d];
            s2 += dyn[j] * yn[j];
        }
        #pragma unroll
        for (int o = 16; o; o >>= 1) s2 += __shfl_xor_sync(0xffffffffu, s2, o);
        #pragma unroll
        for (int j = 0; j < 8; j++)
            dy[t*DIM + lane + 32*j] = inv * (dyn[j] - yn[j] * (s2 * (1.f/DIM)));
    }
    #pragma unroll
    for (int j = 0; j < 8; j++) atomicAdd(&racc[lane + 32*j], ra[j]);
    __syncthreads();
    grn[(long long)cb*DIM + tid] = racc[tid];
}

// ---------------- momentum + decay scan (per element) ----------------
__global__ void scan_kernel(const float* __restrict__ G, const float* __restrict__ W0,
                            float* __restrict__ Wout,
                            const float* __restrict__ momg, const float* __restrict__ decg,
                            int numel)
{
    int e = blockIdx.x * blockDim.x + threadIdx.x;
    int b = blockIdx.y;
    if (e >= numel) return;
    float m = 0.f, W = W0[e];
    #pragma unroll 4
    for (int c = 0; c < NCHK; c++) {
        int cb = b*NCHK + c;
        Wout[(long long)cb*numel + e] = W;          // shifted: weights before chunk c's update
        float gm = momg[cb], gd = decg[cb];
        m = gm * m - G[(long long)cb*numel + e];    // s = -grad
        W = (1.f - gd) * W + m;
    }
}

// ---------------- final: rmsnorm(y2)*rnu + q ----------------
__global__ void final_kernel(const float* __restrict__ y2, const float* __restrict__ qbuf,
                             const float* __restrict__ rnu, float* __restrict__ out)
{
    int cb = blockIdx.x;
    int tid = threadIdx.x, lane = tid & 31, wid = tid >> 5;
    __shared__ float s_rnu[DIM];
    s_rnu[tid] = rnu[(long long)cb*DIM + tid];
    __syncthreads();
    long long base = (long long)cb * CH;
    for (int i = wid; i < CH; i += 8) {
        long long t = base + i;
        float yv[8], ss = 0.f;
        #pragma unroll
        for (int j = 0; j < 8; j++) { yv[j] = y2[t*DIM + lane + 32*j]; ss += yv[j]*yv[j]; }
        #pragma unroll
        for (int o = 16; o; o >>= 1) ss += __shfl_xor_sync(0xffffffffu, ss, o);
        float inv = rsqrtf(ss * (1.f/DIM) + EPSV);
        #pragma unroll
        for (int j = 0; j < 8; j++) {
            int d = lane + 32*j;
            out[t*DIM + d] = yv[j]*inv*s_rnu[d] + qbuf[t*DIM + d];
        }
    }
}

// ---------------- launch ----------------
extern "C" void kernel_launch(void* const* d_in, const int* in_sizes, int n_in,
                              void* d_out, int out_size)
{
    (void)in_sizes; (void)n_in; (void)out_size;
    const float* seq   = (const float*)d_in[0];
    const float* gs    = (const float*)d_in[1];
    const float* gr    = (const float*)d_in[2];
    const float* Wq    = (const float*)d_in[3];
    const float* Wk    = (const float*)d_in[4];
    const float* Wv    = (const float*)d_in[5];
    const float* Wstep = (const float*)d_in[6];
    const float* bstep = (const float*)d_in[7];
    const float* Wmom  = (const float*)d_in[8];
    const float* bmom  = (const float*)d_in[9];
    const float* Wdec  = (const float*)d_in[10];
    const float* bdec  = (const float*)d_in[11];
    const float* w1    = (const float*)d_in[12];
    const float* w2    = (const float*)d_in[13];
    const float* rn    = (const float*)d_in[14];
    float* out = (float*)d_out;

    float *store, *ret, *kbuf, *vbuf, *qbuf, *lr, *momg, *decg;
    float *hbuf, *abuf, *ybuf, *dybuf, *dhbuf, *gw1, *gw2, *grn;
    float *w1u, *w2u, *rnu, *a2, *y2;
    cudaGetSymbolAddress((void**)&store, d_store);
    cudaGetSymbolAddress((void**)&ret,   d_ret);
    cudaGetSymbolAddress((void**)&kbuf,  d_kbuf);
    cudaGetSymbolAddress((void**)&vbuf,  d_vbuf);
    cudaGetSymbolAddress((void**)&qbuf,  d_qbuf);
    cudaGetSymbolAddress((void**)&lr,    d_lr);
    cudaGetSymbolAddress((void**)&momg,  d_momg);
    cudaGetSymbolAddress((void**)&decg,  d_decg);
    cudaGetSymbolAddress((void**)&hbuf,  d_hbuf);
    cudaGetSymbolAddress((void**)&abuf,  d_abuf);
    cudaGetSymbolAddress((void**)&ybuf,  d_ybuf);
    cudaGetSymbolAddress((void**)&dybuf, d_dybuf);
    cudaGetSymbolAddress((void**)&dhbuf, d_dhbuf);
    cudaGetSymbolAddress((void**)&gw1,   d_gw1);
    cudaGetSymbolAddress((void**)&gw2,   d_gw2);
    cudaGetSymbolAddress((void**)&grn,   d_grn);
    cudaGetSymbolAddress((void**)&w1u,   d_w1u);
    cudaGetSymbolAddress((void**)&w2u,   d_w2u);
    cudaGetSymbolAddress((void**)&rnu,   d_rnu);
    cudaGetSymbolAddress((void**)&a2,    d_a2);
    cudaGetSymbolAddress((void**)&y2,    d_y2);

    const long long PW = (long long)DIM * HID;   // 262144

    // 1) rmsnorms, per-token lr, chunk gates
    pre_kernel<<<CBTOT, 256>>>(seq, gs, gr, Wstep, bstep, Wmom, bmom, Wdec, bdec,
                               store, ret, lr, momg, decg);
    // 2) k, v, q projections
    gemm_kernel<false,false,0><<<dim3(4,64,1),256>>>(store, Wk, kbuf, nullptr, nullptr,
        TOKS, DIM, DIM, DIM, DIM, DIM, 0, 0, 0);
    gemm_kernel<false,false,0><<<dim3(4,64,1),256>>>(store, Wv, vbuf, nullptr, nullptr,
        TOKS, DIM, DIM, DIM, DIM, DIM, 0, 0, 0);
    gemm_kernel<false,false,0><<<dim3(4,64,1),256>>>(ret, Wq, qbuf, nullptr, nullptr,
        TOKS, DIM, DIM, DIM, DIM, DIM, 0, 0, 0);
    // 3) forward memory MLP (shared initial weights for all chunks)
    gemm_kernel<false,false,1><<<dim3(16,64,1),256>>>(kbuf, w1, abuf, hbuf, nullptr,
        TOKS, HID, DIM, DIM, HID, HID, 0, 0, 0);
    gemm_kernel<false,false,0><<<dim3(4,64,1),256>>>(abuf, w2, ybuf, nullptr, nullptr,
        TOKS, DIM, HID, HID, DIM, DIM, 0, 0, 0);
    // 4) backward through residual-rmsnorm + per-chunk rn grads
    lossback_kernel<<<CBTOT, 256>>>(ybuf, kbuf, vbuf, lr, rn, dybuf, grn);
    // 5) dh = (dy @ w2^T) * gelu'(h)
    gemm_kernel<false,true,3><<<dim3(16,64,1),256>>>(dybuf, w2, dhbuf, nullptr, hbuf,
        TOKS, HID, DIM, DIM, DIM, HID, 0, 0, 0);
    // 6) per-chunk weight grads (batched outer products over 64 tokens)
    gemm_kernel<true,false,0><<<dim3(16,4,CBTOT),256>>>(kbuf, dhbuf, gw1, nullptr, nullptr,
        DIM, HID, CH, DIM, HID, HID, (long long)CH*DIM, (long long)CH*HID, PW);
    gemm_kernel<true,false,0><<<dim3(4,16,CBTOT),256>>>(abuf, dybuf, gw2, nullptr, nullptr,
        HID, DIM, CH, HID, DIM, DIM, (long long)CH*HID, (long long)CH*DIM, PW);
    // 7) momentum+decay scan, with one-chunk shift baked in
    scan_kernel<<<dim3(1024,BATCH),256>>>(gw1, w1, w1u, momg, decg, (int)PW);
    scan_kernel<<<dim3(1024,BATCH),256>>>(gw2, w2, w2u, momg, decg, (int)PW);
    scan_kernel<<<dim3(1,BATCH),256>>>(grn, rn, rnu, momg, decg, DIM);
    // 8) retrieval with per-chunk weights
    gemm_kernel<false,false,2><<<dim3(16,1,CBTOT),256>>>(qbuf, w1u, a2, nullptr, nullptr,
        CH, HID, DIM, DIM, HID, HID, (long long)CH*DIM, PW, (long long)CH*HID);
    gemm_kernel<false,false,0><<<dim3(4,1,CBTOT),256>>>(a2, w2u, y2, nullptr, nullptr,
        CH, DIM, HID, HID, DIM, DIM, (long long)CH*HID, PW, (long long)CH*DIM);
    // 9) final ResidualNorm
    final_kernel<<<CBTOT, 256>>>(y2, qbuf, rnu, out);
}